// round 14
// baseline (speedup 1.0000x reference)
#include <cuda_runtime.h>
#include <math.h>
#include <stdint.h>

#define NB    4096
#define SEQL  168
#define CF    64
#define NP    96
#define KW    25
#define PI_F  3.14159265358979f

// chunk-contiguous fragment scratch:
// d_xA: [c][kc(7)][mb(256)][kbl(3)][128]   (m16xk8 frag blocks; one CTA stage = contiguous)
// d_MB: [c][kc(7)][np(12)][kbl(3)][128]    (n16xk8 frag blocks)
__device__ float d_xA[(size_t)CF * 7 * 256 * 3 * 128];
__device__ float d_MB[(size_t)CF * 7 * 12 * 3 * 128];
__device__ float d_modT[(size_t)NP * NB];            // [p][b]
__device__ float d_outS[(size_t)CF * NP * NB];       // [c][p][b] gemm scratch
__device__ float d_c12[2 * NP];

__device__ __forceinline__ float to_tf32(float f) {
    uint32_t u;
    asm("cvt.rna.tf32.f32 %0, %1;" : "=r"(u) : "f"(f));
    return __uint_as_float(u);
}
__device__ __forceinline__ uint32_t smem_u32(const void* p) {
    uint32_t a;
    asm("{ .reg .u64 t; cvta.to.shared.u64 t, %1; cvt.u32.u64 %0, t; }" : "=r"(a) : "l"(p));
    return a;
}
__device__ __forceinline__ void mma_tf32(float* d, const uint32_t* a, const uint32_t* b) {
    asm volatile(
        "mma.sync.aligned.m16n8k8.row.col.f32.tf32.tf32.f32 "
        "{%0,%1,%2,%3}, {%4,%5,%6,%7}, {%8,%9}, {%0,%1,%2,%3};"
        : "+f"(d[0]), "+f"(d[1]), "+f"(d[2]), "+f"(d[3])
        : "r"(a[0]), "r"(a[1]), "r"(a[2]), "r"(a[3]), "r"(b[0]), "r"(b[1]));
}
__device__ __forceinline__ void mbar_init(uint32_t a, uint32_t cnt) {
    asm volatile("mbarrier.init.shared.b64 [%0], %1;" :: "r"(a), "r"(cnt) : "memory");
}
__device__ __forceinline__ void mbar_expect_tx(uint32_t a, uint32_t bytes) {
    asm volatile("mbarrier.arrive.expect_tx.shared.b64 _, [%0], %1;"
                 :: "r"(a), "r"(bytes) : "memory");
}
__device__ __forceinline__ void mbar_wait(uint32_t a, uint32_t parity) {
    asm volatile(
        "{\n\t.reg .pred P;\n\t"
        "WL_%=:\n\t"
        "mbarrier.try_wait.parity.acquire.cta.shared::cta.b64 P, [%0], %1, 0x989680;\n\t"
        "@!P bra WL_%=;\n\t}"
        :: "r"(a), "r"(parity) : "memory");
}
__device__ __forceinline__ void mbar_arrive(uint32_t a) {
    asm volatile("mbarrier.arrive.release.cta.shared::cta.b64 _, [%0];" :: "r"(a) : "memory");
}
__device__ __forceinline__ void tma_bulk(uint32_t dst, const void* src, uint32_t bytes,
                                         uint32_t mbar) {
    asm volatile(
        "cp.async.bulk.shared::cta.global.mbarrier::complete_tx::bytes [%0], [%1], %2, [%3];"
        :: "r"(dst), "l"(src), "r"(bytes), "r"(mbar) : "memory");
}

// ---------------------------------------------------------------------------
// quantum helpers
// ---------------------------------------------------------------------------
__device__ __forceinline__ float2 cmulf(float2 a, float2 b) {
    return make_float2(a.x * b.x - a.y * b.y, a.x * b.y + a.y * b.x);
}

__device__ void run_circuit(const float qin[4], const float* __restrict__ w, float2 s[16]) {
#pragma unroll
    for (int i = 0; i < 16; i++) s[i] = make_float2(0.f, 0.f);
    s[0].x = 1.f;
#pragma unroll
    for (int l = 0; l < 3; l++) {
#pragma unroll
        for (int q = 0; q < 4; q++) {
            const int m = 8 >> q;
            float sn, cs; sincosf(0.5f * qin[q], &sn, &cs);
#pragma unroll
            for (int i = 0; i < 16; i++) {
                if ((i & m) == 0) {
                    float2 a0 = s[i], a1 = s[i | m];
                    s[i]     = make_float2(cs * a0.x - sn * a1.x, cs * a0.y - sn * a1.y);
                    s[i | m] = make_float2(sn * a0.x + cs * a1.x, sn * a0.y + cs * a1.y);
                }
            }
        }
#pragma unroll
        for (int q = 0; q < 4; q++) {
            const int m = 8 >> q;
            float phi = w[(l * 4 + q) * 3 + 0];
            float th  = w[(l * 4 + q) * 3 + 1];
            float om  = w[(l * 4 + q) * 3 + 2];
            float st, ct; sincosf(0.5f * th, &st, &ct);
            float s1, c1; sincosf(-0.5f * (phi + om), &s1, &c1);
            float s2, c2; sincosf( 0.5f * (phi - om), &s2, &c2);
            float2 U00 = make_float2( c1 * ct,  s1 * ct);
            float2 U01 = make_float2(-c2 * st, -s2 * st);
            float2 U10 = make_float2( c2 * st, -s2 * st);
            float2 U11 = make_float2( c1 * ct, -s1 * ct);
#pragma unroll
            for (int i = 0; i < 16; i++) {
                if ((i & m) == 0) {
                    float2 a0 = s[i], a1 = s[i | m];
                    float2 n0 = cmulf(U00, a0); float2 t = cmulf(U01, a1);
                    n0.x += t.x; n0.y += t.y;
                    float2 n1 = cmulf(U10, a0); t = cmulf(U11, a1);
                    n1.x += t.x; n1.y += t.y;
                    s[i] = n0; s[i | m] = n1;
                }
            }
        }
#pragma unroll
        for (int q = 0; q < 4; q++) {
            const int cm = 8 >> q;
            const int tm = 8 >> ((q + 1) & 3);
#pragma unroll
            for (int i = 0; i < 16; i++) {
                if ((i & cm) && !(i & tm)) {
                    float2 t = s[i]; s[i] = s[i | tm]; s[i | tm] = t;
                }
            }
        }
    }
}

__device__ __forceinline__ void expvals(const float2 s[16], int pauli, float* o) {
#pragma unroll
    for (int q = 0; q < 4; q++) {
        const int m = 8 >> q;
        float acc = 0.f;
#pragma unroll
        for (int i = 0; i < 16; i++) {
            if ((i & m) == 0) {
                float2 a0 = s[i], a1 = s[i | m];
                if (pauli == 0)      acc += a0.x * a1.x + a0.y * a1.y;
                else if (pauli == 1) acc += a0.x * a1.y - a0.y * a1.x;
                else                 acc += a0.x * a0.x + a0.y * a0.y
                                          - a1.x * a1.x - a1.y * a1.y;
            }
        }
        o[q] = (pauli == 2) ? acc : 2.f * acc;
    }
}

// ---------------------------------------------------------------------------
// Kernel 0 (fused pre-work): heterogeneous blocks.
//   [0, 128)        : mod   (96 active threads)   -> d_modT
//   [128, 640)      : prep (c, p-octet), softmax shared across 12 p -> d_MB, d_c12
//   [640, 3712)     : transpose x2 sub-tiles      -> d_xA
// 5 CTAs/SM (launch_bounds): regs were the occupancy cap at 64.
// ---------------------------------------------------------------------------
#define N_MODB   128
#define N_PREPB  512
#define N_TRB    3072

__global__ __launch_bounds__(256, 5) void pre_k(const float* __restrict__ x,
                      const float* __restrict__ decomp_w,
                      const float* __restrict__ trend_W, const float* __restrict__ trend_b,
                      const float* __restrict__ seas_W,  const float* __restrict__ seas_b,
                      const float* __restrict__ lagc_W,  const float* __restrict__ lagc_b,
                      const float* __restrict__ wx, const float* __restrict__ wy,
                      const float* __restrict__ wz,
                      const float* __restrict__ W1, const float* __restrict__ b1,
                      const float* __restrict__ W2, const float* __restrict__ b2,
                      const float* __restrict__ alpha) {
    __shared__ float sh_raw[8 * 32 * 33];      // 33.8KB
    const int bid = blockIdx.x;
    const int tid = threadIdx.x;

    if (bid < N_MODB) {
        // ================= mod path =================
        float (*feats_s)[13] = (float (*)[13])sh_raw;
        const int bl = tid & 31;
        const int r  = tid >> 5;
        const bool act = tid < 96;
        const int b  = bid * 32 + bl;
        float h[12];
        if (act) {
            const int lags[11] = {167, 166, 165, 164, 163, 162, 145, 144, 143, 1, 0};
            float lag[11];
#pragma unroll
            for (int j = 0; j < 11; j++)
                lag[j] = x[(size_t)b * (SEQL * CF) + lags[j] * CF + (CF - 1)];
            float qin[4];
#pragma unroll
            for (int q = 0; q < 4; q++) {
                float s = lagc_b[q];
#pragma unroll
                for (int j = 0; j < 11; j++) s += lag[j] * lagc_W[q * 11 + j];
                qin[q] = tanhf(s) * PI_F;
            }
            const float* w = (r == 0) ? wx : (r == 1) ? wy : wz;
            float2 st[16];
            float f4[4];
            run_circuit(qin, w, st);
            expvals(st, r, f4);
#pragma unroll
            for (int q = 0; q < 4; q++) feats_s[bl][r * 4 + q] = f4[q];
        }
        __syncthreads();
        if (act) {
            float feats[12];
#pragma unroll
            for (int j = 0; j < 12; j++) feats[j] = feats_s[bl][j];
#pragma unroll
            for (int i = 0; i < 12; i++) {
                float s = b1[i];
#pragma unroll
                for (int j = 0; j < 12; j++) s += feats[j] * W1[i * 12 + j];
                h[i] = fmaxf(s, 0.f);
            }
            for (int pp = 0; pp < 32; pp++) {
                int p = r * 32 + pp;
                float s = b2[p];
#pragma unroll
                for (int i = 0; i < 12; i++) s += h[i] * W2[p * 12 + i];
                d_modT[(size_t)p * NB + b] = tanhf(s);
            }
        }
    } else if (bid < N_MODB + N_PREPB) {
        // ================= prep path: (c, p-octet) =================
        const int q0 = bid - N_MODB;
        const int c  = q0 >> 3;
        const int pg = q0 & 7;
        const int j  = tid;
        float* ker = sh_raw;
        float* a_sh = sh_raw + KW;
        if (j == 0) {
            float mx = -1e30f;
            for (int k = 0; k < KW; k++) mx = fmaxf(mx, decomp_w[c * KW + k]);
            float sum = 0.f, e[KW];
            for (int k = 0; k < KW; k++) { e[k] = expf(decomp_w[c * KW + k] - mx); sum += e[k]; }
            for (int k = 0; k < KW; k++) ker[k] = e[k] / sum;
            a_sh[0] = 1.f / (1.f + expf(-alpha[0]));
        }
        __syncthreads();
        if (j < SEQL) {
            const float a = a_sh[0];
            const int kb = j >> 3, kk = j & 7, t = kk & 3, th = kk >> 2;
            const int kc = kb / 3, kr = kb - kc * 3;
            for (int pi = 0; pi < 12; pi++) {
                const int p = pg * 12 + pi;
                const float* sW = seas_W + p * SEQL;
                const float* tW = trend_W + p * SEQL;
                float sA = 0.f, sB = 0.f;
                if (j == 0) {
                    for (int k = 0; k <= 12; k++) {
                        float wk = ker[k];
                        for (int l = 0; l <= 12 - k; l++) { sA += wk * sW[l]; sB += wk * tW[l]; }
                    }
                } else if (j == SEQL - 1) {
                    for (int k = 12; k < KW; k++) {
                        float wk = ker[k];
                        for (int l = 179 - k; l < SEQL; l++) { sA += wk * sW[l]; sB += wk * tW[l]; }
                    }
                } else {
                    for (int k = 0; k < KW; k++) {
                        int l = j + 12 - k;
                        if (l >= 0 && l < SEQL) { float wk = ker[k]; sA += wk * sW[l]; sB += wk * tW[l]; }
                    }
                }
                float A = sW[j] - sA;
                float M1 = to_tf32(a * A + (1.f - a) * sB);   // n = 2p
                float M2 = to_tf32(a * A);                    // n = 2p+1
#pragma unroll
                for (int h2 = 0; h2 < 2; h2++) {
                    int n = 2 * p + h2;
                    int np = n >> 4, nn = n & 15, qq = nn >> 3, g = nn & 7;
                    int lane = g * 4 + t, reg = 2 * qq + th;
                    d_MB[((((size_t)c * 7 + kc) * 12 + np) * 3 + kr) * 128 + lane * 4 + reg]
                        = h2 ? M2 : M1;
                }
                if (c == 0 && j == 0) {
                    d_c12[p]      = a * seas_b[p] + (1.f - a) * trend_b[p];
                    d_c12[NP + p] = a * seas_b[p];
                }
            }
        }
    } else {
        // ================= transpose path (2 sub-tiles) =================
        float (*sh)[32][33] = (float (*)[32][33])sh_raw;
        const int t  = bid - (N_MODB + N_PREPB);
        const int c0 = (t & 7) * 8;
        const int l0 = ((t >> 3) % 6) * 32;
        const int bbase = (t / 48) * 64;
        const float4* x4 = (const float4*)x;
        float4* o4 = (float4*)d_xA;
        for (int sub = 0; sub < 2; sub++) {
            const int b0 = bbase + sub * 32;
#pragma unroll
            for (int it = 0; it < 8; it++) {
                int i = it * 256 + tid;
                int c4i = i & 1, l = (i >> 1) & 31, b = i >> 6;
                int lg = l0 + l;
                float4 v = make_float4(0.f, 0.f, 0.f, 0.f);
                if (lg < SEQL)
                    v = x4[(size_t)(b0 + b) * (SEQL * 16) + (size_t)lg * 16 + (c0 >> 2) + c4i];
                sh[c4i * 4 + 0][l][b] = to_tf32(v.x);
                sh[c4i * 4 + 1][l][b] = to_tf32(v.y);
                sh[c4i * 4 + 2][l][b] = to_tf32(v.z);
                sh[c4i * 4 + 3][l][b] = to_tf32(v.w);
            }
            __syncthreads();
#pragma unroll
            for (int it = 0; it < 8; it++) {
                int i = it * 256 + tid;
                int lane = i & 31, kbl = (i >> 5) & 3, mbl = (i >> 7) & 1, cl = i >> 8;
                int kb_g = (l0 >> 3) + kbl;
                if (kb_g >= 21) continue;
                int kc = kb_g / 3, kr = kb_g - kc * 3;
                int g = lane >> 2, tg = lane & 3;
                float4 w;
                w.x = sh[cl][kbl * 8 + tg]    [mbl * 16 + g];
                w.y = sh[cl][kbl * 8 + tg]    [mbl * 16 + g + 8];
                w.z = sh[cl][kbl * 8 + tg + 4][mbl * 16 + g];
                w.w = sh[cl][kbl * 8 + tg + 4][mbl * 16 + g + 8];
                size_t idx4 = ((((size_t)(c0 + cl) * 7 + kc) * 256 + (b0 >> 4) + mbl) * 3 + kr)
                            * 32 + lane;
                o4[idx4] = w;
            }
            __syncthreads();
        }
    }
}

// ---------------------------------------------------------------------------
// Kernel 1: persistent TF32 mma.sync GEMM; continuous 7-stage TMA ring.
// 544 threads: warps 0-15 consumers (4m x 4n, warp tile m32 x n48),
// warp 16 producer. Tile = (c, 128 batches); NTILES = 2048.
// ---------------------------------------------------------------------------
#define STAGE_F4   1920                  // A 768 + B 1152 float4
#define STAGE_B    (STAGE_F4 * 16)       // 30720 bytes
#define A_BYTES    12288
#define B_BYTES    18432
#define NCHUNK     7
#define NTILES     2048

__global__ __launch_bounds__(544, 1) void gemm_k() {
    extern __shared__ __align__(16) float4 sm4[];
    __shared__ __align__(8) uint64_t mbar[2 * NCHUNK];  // full[7], empty[7]

    const int tid = threadIdx.x;
    const int wid  = tid >> 5;
    const int lane = tid & 31;
    const int bid = blockIdx.x;
    const int stride = gridDim.x;

    const uint32_t smb = smem_u32(sm4);
    const uint32_t mbF = smem_u32(&mbar[0]);
    const uint32_t mbE = smem_u32(&mbar[NCHUNK]);

    if (tid == 0) {
#pragma unroll
        for (int s = 0; s < NCHUNK; s++) {
            mbar_init(mbF + 8 * s, 1);   // expect_tx arrival + tx bytes
            mbar_init(mbE + 8 * s, 16);  // one arrive per consumer warp
        }
    }
    __syncthreads();

    if (wid == 16) {
        // ---- producer warp: keep the ring one tile ahead ----
        int it = 0;
        for (int t = bid; t < NTILES; t += stride) {
            const int c   = t >> 5;
            const int mb0 = (t & 31) * 8;
#pragma unroll
            for (int kc = 0; kc < NCHUNK; kc++) {
                if (it > 0) mbar_wait(mbE + 8 * kc, (it - 1) & 1);
                if (lane == 0) {
                    const uint32_t D0 = smb + kc * STAGE_B;
                    const float* srcA = d_xA + (((size_t)c * 7 + kc) * 256 + mb0) * 384;
                    const float* srcB = d_MB + (((size_t)c * 7 + kc) * 12) * 384;
                    mbar_expect_tx(mbF + 8 * kc, STAGE_B);
                    tma_bulk(D0, srcA, A_BYTES, mbF + 8 * kc);
                    tma_bulk(D0 + A_BYTES, srcB, B_BYTES, mbF + 8 * kc);
                }
            }
            it++;
        }
    } else {
        // ---- consumer warps 0..15 : 4m x 4n ----
        const int warp_mb = (wid & 3) * 2;
        const int warp_np = (wid >> 2) * 3;
        const int gid = lane >> 2;
        const int tig = lane & 3;
        int it = 0;

        for (int t = bid; t < NTILES; t += stride) {
            const int c  = t >> 5;
            const int b0 = (t & 31) * 128;

            float acc[2][6][4];
#pragma unroll
            for (int mi = 0; mi < 2; mi++)
#pragma unroll
                for (int ni = 0; ni < 6; ni++)
#pragma unroll
                    for (int r = 0; r < 4; r++) acc[mi][ni][r] = 0.f;

#pragma unroll 1
            for (int kc = 0; kc < NCHUNK; kc++) {
                mbar_wait(mbF + 8 * kc, it & 1);
                const float4* As = sm4 + kc * STAGE_F4;
                const float4* Bs = As + 768;
#pragma unroll
                for (int kbl = 0; kbl < 3; kbl++) {
                    float4 af4[2], bf4[3];
#pragma unroll
                    for (int mi = 0; mi < 2; mi++)
                        af4[mi] = As[((warp_mb + mi) * 3 + kbl) * 32 + lane];
#pragma unroll
                    for (int npj = 0; npj < 3; npj++)
                        bf4[npj] = Bs[((warp_np + npj) * 3 + kbl) * 32 + lane];
#pragma unroll
                    for (int mi = 0; mi < 2; mi++) {
                        const uint32_t* a = (const uint32_t*)&af4[mi];
#pragma unroll
                        for (int npj = 0; npj < 3; npj++) {
                            const uint32_t* b = (const uint32_t*)&bf4[npj];
                            mma_tf32(acc[mi][npj * 2 + 0], a, b);
                            mma_tf32(acc[mi][npj * 2 + 1], a, b + 2);
                        }
                    }
                }
                if (lane == 0) mbar_arrive(mbE + 8 * kc);
            }

            // epilogue -> d_outS[c][p][b]
            const int pbase = warp_np * 8;
            float* outc = d_outS + (size_t)c * NP * NB;
#pragma unroll
            for (int ni = 0; ni < 6; ni++) {
                const int p = pbase + ni * 4 + tig;
                const float C1 = d_c12[p];
                const float C2 = d_c12[NP + p];
                const float* modp = d_modT + (size_t)p * NB;
                float* outp = outc + (size_t)p * NB;
#pragma unroll
                for (int mi = 0; mi < 2; mi++) {
#pragma unroll
                    for (int h = 0; h < 2; h++) {
                        const int b = b0 + (wid & 3) * 32 + mi * 16 + gid + h * 8;
                        const float y1 = acc[mi][ni][2 * h];
                        const float y2 = acc[mi][ni][2 * h + 1];
                        outp[b] = y1 + C1 + modp[b] * (y2 + C2);
                    }
                }
            }
            it++;
        }
    }
}

// ---------------------------------------------------------------------------
// Kernel 2: d_outS[c][p][b] -> out[b][p][c]  (coalesced both sides)
// ---------------------------------------------------------------------------
__global__ __launch_bounds__(256) void outT_k(float* __restrict__ out) {
    __shared__ float tile[64][65];
    const int b0 = blockIdx.x * 64;
    const int p  = blockIdx.y;
    const int tid = threadIdx.x;
#pragma unroll
    for (int it = 0; it < 4; it++) {
        int i = it * 256 + tid;
        int cc = i >> 4, q = i & 15;
        float4 v = *(const float4*)(d_outS + (((size_t)cc * NP + p) * NB) + b0 + q * 4);
        tile[cc][q * 4 + 0] = v.x;
        tile[cc][q * 4 + 1] = v.y;
        tile[cc][q * 4 + 2] = v.z;
        tile[cc][q * 4 + 3] = v.w;
    }
    __syncthreads();
#pragma unroll
    for (int it = 0; it < 4; it++) {
        int i = it * 256 + tid;
        int b = i >> 4, q = i & 15;
        float4 w;
        w.x = tile[q * 4 + 0][b];
        w.y = tile[q * 4 + 1][b];
        w.z = tile[q * 4 + 2][b];
        w.w = tile[q * 4 + 3][b];
        *(float4*)(out + (size_t)(b0 + b) * (NP * CF) + (size_t)p * CF + q * 4) = w;
    }
}

// ---------------------------------------------------------------------------
extern "C" void kernel_launch(void* const* d_in, const int* in_sizes, int n_in,
                              void* d_out, int out_size) {
    const float* x        = (const float*)d_in[0];
    const float* decomp_w = (const float*)d_in[1];
    const float* trend_W  = (const float*)d_in[2];
    const float* trend_b  = (const float*)d_in[3];
    const float* seas_W   = (const float*)d_in[4];
    const float* seas_b   = (const float*)d_in[5];
    const float* lagc_W   = (const float*)d_in[6];
    const float* lagc_b   = (const float*)d_in[7];
    const float* wx       = (const float*)d_in[8];
    const float* wy       = (const float*)d_in[9];
    const float* wz       = (const float*)d_in[10];
    const float* W1       = (const float*)d_in[11];
    const float* b1       = (const float*)d_in[12];
    const float* W2       = (const float*)d_in[13];
    const float* b2       = (const float*)d_in[14];
    const float* alpha    = (const float*)d_in[15];
    float* out = (float*)d_out;

    static int n_sm = 0;
    if (n_sm == 0) {
        cudaDeviceGetAttribute(&n_sm, cudaDevAttrMultiProcessorCount, 0);
        if (n_sm <= 0) n_sm = 148;
        cudaFuncSetAttribute(gemm_k, cudaFuncAttributeMaxDynamicSharedMemorySize,
                             NCHUNK * STAGE_B);
    }

    pre_k<<<N_MODB + N_PREPB + N_TRB, 256>>>(x, decomp_w, trend_W, trend_b, seas_W, seas_b,
                                             lagc_W, lagc_b, wx, wy, wz,
                                             W1, b1, W2, b2, alpha);
    gemm_k<<<n_sm, 544, NCHUNK * STAGE_B>>>();
    outT_k<<<dim3(64, 96), 256>>>(out);
}

// round 15
// speedup vs baseline: 1.0554x; 1.0554x over previous
#include <cuda_runtime.h>
#include <math.h>
#include <stdint.h>

#define NB    4096
#define SEQL  168
#define CF    64
#define NP    96
#define KW    25
#define PI_F  3.14159265358979f

// chunk-contiguous fragment scratch:
// d_xA: [c][kc(7)][mb(256)][kbl(3)][128]   (m16xk8 frag blocks; one CTA stage = contiguous)
// d_MB: [c][kc(7)][np(12)][kbl(3)][128]    (n16xk8 frag blocks)
__device__ float d_xA[(size_t)CF * 7 * 256 * 3 * 128];
__device__ float d_MB[(size_t)CF * 7 * 12 * 3 * 128];
__device__ float d_modT[(size_t)NP * NB];            // [p][b]
__device__ float d_outS[(size_t)CF * NP * NB];       // [c][p][b] gemm scratch
__device__ float d_c12[2 * NP];

__device__ __forceinline__ float to_tf32(float f) {
    uint32_t u;
    asm("cvt.rna.tf32.f32 %0, %1;" : "=r"(u) : "f"(f));
    return __uint_as_float(u);
}
__device__ __forceinline__ uint32_t smem_u32(const void* p) {
    uint32_t a;
    asm("{ .reg .u64 t; cvta.to.shared.u64 t, %1; cvt.u32.u64 %0, t; }" : "=r"(a) : "l"(p));
    return a;
}
__device__ __forceinline__ void mma_tf32(float* d, const uint32_t* a, const uint32_t* b) {
    asm volatile(
        "mma.sync.aligned.m16n8k8.row.col.f32.tf32.tf32.f32 "
        "{%0,%1,%2,%3}, {%4,%5,%6,%7}, {%8,%9}, {%0,%1,%2,%3};"
        : "+f"(d[0]), "+f"(d[1]), "+f"(d[2]), "+f"(d[3])
        : "r"(a[0]), "r"(a[1]), "r"(a[2]), "r"(a[3]), "r"(b[0]), "r"(b[1]));
}
__device__ __forceinline__ void mbar_init(uint32_t a, uint32_t cnt) {
    asm volatile("mbarrier.init.shared.b64 [%0], %1;" :: "r"(a), "r"(cnt) : "memory");
}
__device__ __forceinline__ void mbar_expect_tx(uint32_t a, uint32_t bytes) {
    asm volatile("mbarrier.arrive.expect_tx.shared.b64 _, [%0], %1;"
                 :: "r"(a), "r"(bytes) : "memory");
}
__device__ __forceinline__ void mbar_wait(uint32_t a, uint32_t parity) {
    asm volatile(
        "{\n\t.reg .pred P;\n\t"
        "WL_%=:\n\t"
        "mbarrier.try_wait.parity.acquire.cta.shared::cta.b64 P, [%0], %1, 0x989680;\n\t"
        "@!P bra WL_%=;\n\t}"
        :: "r"(a), "r"(parity) : "memory");
}
__device__ __forceinline__ void mbar_arrive(uint32_t a) {
    asm volatile("mbarrier.arrive.release.cta.shared::cta.b64 _, [%0];" :: "r"(a) : "memory");
}
__device__ __forceinline__ void tma_bulk(uint32_t dst, const void* src, uint32_t bytes,
                                         uint32_t mbar) {
    asm volatile(
        "cp.async.bulk.shared::cta.global.mbarrier::complete_tx::bytes [%0], [%1], %2, [%3];"
        :: "r"(dst), "l"(src), "r"(bytes), "r"(mbar) : "memory");
}

// ---------------------------------------------------------------------------
// quantum helpers
// ---------------------------------------------------------------------------
__device__ __forceinline__ float2 cmulf(float2 a, float2 b) {
    return make_float2(a.x * b.x - a.y * b.y, a.x * b.y + a.y * b.x);
}

__device__ void run_circuit(const float qin[4], const float* __restrict__ w, float2 s[16]) {
#pragma unroll
    for (int i = 0; i < 16; i++) s[i] = make_float2(0.f, 0.f);
    s[0].x = 1.f;
#pragma unroll
    for (int l = 0; l < 3; l++) {
#pragma unroll
        for (int q = 0; q < 4; q++) {
            const int m = 8 >> q;
            float sn, cs; sincosf(0.5f * qin[q], &sn, &cs);
#pragma unroll
            for (int i = 0; i < 16; i++) {
                if ((i & m) == 0) {
                    float2 a0 = s[i], a1 = s[i | m];
                    s[i]     = make_float2(cs * a0.x - sn * a1.x, cs * a0.y - sn * a1.y);
                    s[i | m] = make_float2(sn * a0.x + cs * a1.x, sn * a0.y + cs * a1.y);
                }
            }
        }
#pragma unroll
        for (int q = 0; q < 4; q++) {
            const int m = 8 >> q;
            float phi = w[(l * 4 + q) * 3 + 0];
            float th  = w[(l * 4 + q) * 3 + 1];
            float om  = w[(l * 4 + q) * 3 + 2];
            float st, ct; sincosf(0.5f * th, &st, &ct);
            float s1, c1; sincosf(-0.5f * (phi + om), &s1, &c1);
            float s2, c2; sincosf( 0.5f * (phi - om), &s2, &c2);
            float2 U00 = make_float2( c1 * ct,  s1 * ct);
            float2 U01 = make_float2(-c2 * st, -s2 * st);
            float2 U10 = make_float2( c2 * st, -s2 * st);
            float2 U11 = make_float2( c1 * ct, -s1 * ct);
#pragma unroll
            for (int i = 0; i < 16; i++) {
                if ((i & m) == 0) {
                    float2 a0 = s[i], a1 = s[i | m];
                    float2 n0 = cmulf(U00, a0); float2 t = cmulf(U01, a1);
                    n0.x += t.x; n0.y += t.y;
                    float2 n1 = cmulf(U10, a0); t = cmulf(U11, a1);
                    n1.x += t.x; n1.y += t.y;
                    s[i] = n0; s[i | m] = n1;
                }
            }
        }
#pragma unroll
        for (int q = 0; q < 4; q++) {
            const int cm = 8 >> q;
            const int tm = 8 >> ((q + 1) & 3);
#pragma unroll
            for (int i = 0; i < 16; i++) {
                if ((i & cm) && !(i & tm)) {
                    float2 t = s[i]; s[i] = s[i | tm]; s[i | tm] = t;
                }
            }
        }
    }
}

__device__ __forceinline__ void expvals(const float2 s[16], int pauli, float* o) {
#pragma unroll
    for (int q = 0; q < 4; q++) {
        const int m = 8 >> q;
        float acc = 0.f;
#pragma unroll
        for (int i = 0; i < 16; i++) {
            if ((i & m) == 0) {
                float2 a0 = s[i], a1 = s[i | m];
                if (pauli == 0)      acc += a0.x * a1.x + a0.y * a1.y;
                else if (pauli == 1) acc += a0.x * a1.y - a0.y * a1.x;
                else                 acc += a0.x * a0.x + a0.y * a0.y
                                          - a1.x * a1.x - a1.y * a1.y;
            }
        }
        o[q] = (pauli == 2) ? acc : 2.f * acc;
    }
}

// ---------------------------------------------------------------------------
// Kernel 0 (fused pre-work): heterogeneous blocks.
//   [0, 128)        : mod   (96 active threads)   -> d_modT
//   [128, 640)      : prep (c, p-octet)           -> d_MB, d_c12
//   [640, 4224)     : transpose [8c][24l][64b] x2 sub-tiles -> d_xA
// smem 25.3KB + regs<=48 -> 5 CTAs/SM (smem carveout 164KB was the R13/14 cap).
// ---------------------------------------------------------------------------
#define N_MODB   128
#define N_PREPB  512
#define N_TRB    3584          // 8 cgroups x 7 ltiles x 64 branges

__global__ __launch_bounds__(256, 5) void pre_k(const float* __restrict__ x,
                      const float* __restrict__ decomp_w,
                      const float* __restrict__ trend_W, const float* __restrict__ trend_b,
                      const float* __restrict__ seas_W,  const float* __restrict__ seas_b,
                      const float* __restrict__ lagc_W,  const float* __restrict__ lagc_b,
                      const float* __restrict__ wx, const float* __restrict__ wy,
                      const float* __restrict__ wz,
                      const float* __restrict__ W1, const float* __restrict__ b1,
                      const float* __restrict__ W2, const float* __restrict__ b2,
                      const float* __restrict__ alpha) {
    __shared__ float sh_raw[8 * 24 * 33];      // 25.3KB
    const int bid = blockIdx.x;
    const int tid = threadIdx.x;

    if (bid < N_MODB) {
        // ================= mod path =================
        float (*feats_s)[13] = (float (*)[13])sh_raw;
        const int bl = tid & 31;
        const int r  = tid >> 5;
        const bool act = tid < 96;
        const int b  = bid * 32 + bl;
        float h[12];
        if (act) {
            const int lags[11] = {167, 166, 165, 164, 163, 162, 145, 144, 143, 1, 0};
            float lag[11];
#pragma unroll
            for (int j = 0; j < 11; j++)
                lag[j] = x[(size_t)b * (SEQL * CF) + lags[j] * CF + (CF - 1)];
            float qin[4];
#pragma unroll
            for (int q = 0; q < 4; q++) {
                float s = lagc_b[q];
#pragma unroll
                for (int j = 0; j < 11; j++) s += lag[j] * lagc_W[q * 11 + j];
                qin[q] = tanhf(s) * PI_F;
            }
            const float* w = (r == 0) ? wx : (r == 1) ? wy : wz;
            float2 st[16];
            float f4[4];
            run_circuit(qin, w, st);
            expvals(st, r, f4);
#pragma unroll
            for (int q = 0; q < 4; q++) feats_s[bl][r * 4 + q] = f4[q];
        }
        __syncthreads();
        if (act) {
            float feats[12];
#pragma unroll
            for (int j = 0; j < 12; j++) feats[j] = feats_s[bl][j];
#pragma unroll
            for (int i = 0; i < 12; i++) {
                float s = b1[i];
#pragma unroll
                for (int j = 0; j < 12; j++) s += feats[j] * W1[i * 12 + j];
                h[i] = fmaxf(s, 0.f);
            }
            for (int pp = 0; pp < 32; pp++) {
                int p = r * 32 + pp;
                float s = b2[p];
#pragma unroll
                for (int i = 0; i < 12; i++) s += h[i] * W2[p * 12 + i];
                d_modT[(size_t)p * NB + b] = tanhf(s);
            }
        }
    } else if (bid < N_MODB + N_PREPB) {
        // ================= prep path: (c, p-octet) =================
        const int q0 = bid - N_MODB;
        const int c  = q0 >> 3;
        const int pg = q0 & 7;
        const int j  = tid;
        float* ker = sh_raw;
        float* a_sh = sh_raw + KW;
        if (j == 0) {
            float mx = -1e30f;
            for (int k = 0; k < KW; k++) mx = fmaxf(mx, decomp_w[c * KW + k]);
            float sum = 0.f, e[KW];
            for (int k = 0; k < KW; k++) { e[k] = expf(decomp_w[c * KW + k] - mx); sum += e[k]; }
            for (int k = 0; k < KW; k++) ker[k] = e[k] / sum;
            a_sh[0] = 1.f / (1.f + expf(-alpha[0]));
        }
        __syncthreads();
        if (j < SEQL) {
            const float a = a_sh[0];
            const int kb = j >> 3, kk = j & 7, t = kk & 3, th = kk >> 2;
            const int kc = kb / 3, kr = kb - kc * 3;
            for (int pi = 0; pi < 12; pi++) {
                const int p = pg * 12 + pi;
                const float* sW = seas_W + p * SEQL;
                const float* tW = trend_W + p * SEQL;
                float sA = 0.f, sB = 0.f;
                if (j == 0) {
                    for (int k = 0; k <= 12; k++) {
                        float wk = ker[k];
                        for (int l = 0; l <= 12 - k; l++) { sA += wk * sW[l]; sB += wk * tW[l]; }
                    }
                } else if (j == SEQL - 1) {
                    for (int k = 12; k < KW; k++) {
                        float wk = ker[k];
                        for (int l = 179 - k; l < SEQL; l++) { sA += wk * sW[l]; sB += wk * tW[l]; }
                    }
                } else {
                    for (int k = 0; k < KW; k++) {
                        int l = j + 12 - k;
                        if (l >= 0 && l < SEQL) { float wk = ker[k]; sA += wk * sW[l]; sB += wk * tW[l]; }
                    }
                }
                float A = sW[j] - sA;
                float M1 = to_tf32(a * A + (1.f - a) * sB);   // n = 2p
                float M2 = to_tf32(a * A);                    // n = 2p+1
#pragma unroll
                for (int h2 = 0; h2 < 2; h2++) {
                    int n = 2 * p + h2;
                    int np = n >> 4, nn = n & 15, qq = nn >> 3, g = nn & 7;
                    int lane = g * 4 + t, reg = 2 * qq + th;
                    d_MB[((((size_t)c * 7 + kc) * 12 + np) * 3 + kr) * 128 + lane * 4 + reg]
                        = h2 ? M2 : M1;
                }
                if (c == 0 && j == 0) {
                    d_c12[p]      = a * seas_b[p] + (1.f - a) * trend_b[p];
                    d_c12[NP + p] = a * seas_b[p];
                }
            }
        }
    } else {
        // ================= transpose path: [8c][24l][32b] x 2 sub-tiles ======
        float (*sh)[24][33] = (float (*)[24][33])sh_raw;
        const int t  = bid - (N_MODB + N_PREPB);
        const int c0 = (t & 7) * 8;
        const int lt = (t >> 3) % 7;         // l-tile = kc chunk
        const int l0 = lt * 24;
        const int bbase = (t / 56) * 64;
        const float4* x4 = (const float4*)x;
        float4* o4 = (float4*)d_xA;
        for (int sub = 0; sub < 2; sub++) {
            const int b0 = bbase + sub * 32;
            // load: 1536 float4 (no predication: l0+l <= 167 always)
#pragma unroll
            for (int it = 0; it < 6; it++) {
                int i = it * 256 + tid;
                int b = i / 48, rem = i % 48;
                int l = rem >> 1, c4i = rem & 1;
                float4 v = x4[(size_t)(b0 + b) * (SEQL * 16) + (size_t)(l0 + l) * 16
                              + (c0 >> 2) + c4i];
                sh[c4i * 4 + 0][l][b] = to_tf32(v.x);
                sh[c4i * 4 + 1][l][b] = to_tf32(v.y);
                sh[c4i * 4 + 2][l][b] = to_tf32(v.z);
                sh[c4i * 4 + 3][l][b] = to_tf32(v.w);
            }
            __syncthreads();
            // write fragments: 1536 float4
#pragma unroll
            for (int it = 0; it < 6; it++) {
                int i = it * 256 + tid;
                int lane = i & 31, j2 = i >> 5;
                int kbl = j2 % 3, mbl = (j2 / 3) & 1, cl = j2 / 6;
                int g = lane >> 2, tg = lane & 3;
                float4 w;
                w.x = sh[cl][kbl * 8 + tg]    [mbl * 16 + g];
                w.y = sh[cl][kbl * 8 + tg]    [mbl * 16 + g + 8];
                w.z = sh[cl][kbl * 8 + tg + 4][mbl * 16 + g];
                w.w = sh[cl][kbl * 8 + tg + 4][mbl * 16 + g + 8];
                size_t idx4 = ((((size_t)(c0 + cl) * 7 + lt) * 256 + (b0 >> 4) + mbl) * 3 + kbl)
                            * 32 + lane;
                o4[idx4] = w;
            }
            __syncthreads();
        }
    }
}

// ---------------------------------------------------------------------------
// Kernel 1: persistent TF32 mma.sync GEMM; continuous 7-stage TMA ring.
// 544 threads: warps 0-15 consumers (4m x 4n, warp tile m32 x n48),
// warp 16 producer. Tile = (c, 128 batches); NTILES = 2048.
// ---------------------------------------------------------------------------
#define STAGE_F4   1920                  // A 768 + B 1152 float4
#define STAGE_B    (STAGE_F4 * 16)       // 30720 bytes
#define A_BYTES    12288
#define B_BYTES    18432
#define NCHUNK     7
#define NTILES     2048

__global__ __launch_bounds__(544, 1) void gemm_k() {
    extern __shared__ __align__(16) float4 sm4[];
    __shared__ __align__(8) uint64_t mbar[2 * NCHUNK];  // full[7], empty[7]

    const int tid = threadIdx.x;
    const int wid  = tid >> 5;
    const int lane = tid & 31;
    const int bid = blockIdx.x;
    const int stride = gridDim.x;

    const uint32_t smb = smem_u32(sm4);
    const uint32_t mbF = smem_u32(&mbar[0]);
    const uint32_t mbE = smem_u32(&mbar[NCHUNK]);

    if (tid == 0) {
#pragma unroll
        for (int s = 0; s < NCHUNK; s++) {
            mbar_init(mbF + 8 * s, 1);   // expect_tx arrival + tx bytes
            mbar_init(mbE + 8 * s, 16);  // one arrive per consumer warp
        }
    }
    __syncthreads();

    if (wid == 16) {
        // ---- producer warp: keep the ring one tile ahead ----
        int it = 0;
        for (int t = bid; t < NTILES; t += stride) {
            const int c   = t >> 5;
            const int mb0 = (t & 31) * 8;
#pragma unroll
            for (int kc = 0; kc < NCHUNK; kc++) {
                if (it > 0) mbar_wait(mbE + 8 * kc, (it - 1) & 1);
                if (lane == 0) {
                    const uint32_t D0 = smb + kc * STAGE_B;
                    const float* srcA = d_xA + (((size_t)c * 7 + kc) * 256 + mb0) * 384;
                    const float* srcB = d_MB + (((size_t)c * 7 + kc) * 12) * 384;
                    mbar_expect_tx(mbF + 8 * kc, STAGE_B);
                    tma_bulk(D0, srcA, A_BYTES, mbF + 8 * kc);
                    tma_bulk(D0 + A_BYTES, srcB, B_BYTES, mbF + 8 * kc);
                }
            }
            it++;
        }
    } else {
        // ---- consumer warps 0..15 : 4m x 4n ----
        const int warp_mb = (wid & 3) * 2;
        const int warp_np = (wid >> 2) * 3;
        const int gid = lane >> 2;
        const int tig = lane & 3;
        int it = 0;

        for (int t = bid; t < NTILES; t += stride) {
            const int c  = t >> 5;
            const int b0 = (t & 31) * 128;

            float acc[2][6][4];
#pragma unroll
            for (int mi = 0; mi < 2; mi++)
#pragma unroll
                for (int ni = 0; ni < 6; ni++)
#pragma unroll
                    for (int r = 0; r < 4; r++) acc[mi][ni][r] = 0.f;

#pragma unroll 1
            for (int kc = 0; kc < NCHUNK; kc++) {
                mbar_wait(mbF + 8 * kc, it & 1);
                const float4* As = sm4 + kc * STAGE_F4;
                const float4* Bs = As + 768;
#pragma unroll
                for (int kbl = 0; kbl < 3; kbl++) {
                    float4 af4[2], bf4[3];
#pragma unroll
                    for (int mi = 0; mi < 2; mi++)
                        af4[mi] = As[((warp_mb + mi) * 3 + kbl) * 32 + lane];
#pragma unroll
                    for (int npj = 0; npj < 3; npj++)
                        bf4[npj] = Bs[((warp_np + npj) * 3 + kbl) * 32 + lane];
#pragma unroll
                    for (int mi = 0; mi < 2; mi++) {
                        const uint32_t* a = (const uint32_t*)&af4[mi];
#pragma unroll
                        for (int npj = 0; npj < 3; npj++) {
                            const uint32_t* b = (const uint32_t*)&bf4[npj];
                            mma_tf32(acc[mi][npj * 2 + 0], a, b);
                            mma_tf32(acc[mi][npj * 2 + 1], a, b + 2);
                        }
                    }
                }
                if (lane == 0) mbar_arrive(mbE + 8 * kc);
            }

            // epilogue -> d_outS[c][p][b]
            const int pbase = warp_np * 8;
            float* outc = d_outS + (size_t)c * NP * NB;
#pragma unroll
            for (int ni = 0; ni < 6; ni++) {
                const int p = pbase + ni * 4 + tig;
                const float C1 = d_c12[p];
                const float C2 = d_c12[NP + p];
                const float* modp = d_modT + (size_t)p * NB;
                float* outp = outc + (size_t)p * NB;
#pragma unroll
                for (int mi = 0; mi < 2; mi++) {
#pragma unroll
                    for (int h = 0; h < 2; h++) {
                        const int b = b0 + (wid & 3) * 32 + mi * 16 + gid + h * 8;
                        const float y1 = acc[mi][ni][2 * h];
                        const float y2 = acc[mi][ni][2 * h + 1];
                        outp[b] = y1 + C1 + modp[b] * (y2 + C2);
                    }
                }
            }
            it++;
        }
    }
}

// ---------------------------------------------------------------------------
// Kernel 2: d_outS[c][p][b] -> out[b][p][c]  (coalesced both sides)
// ---------------------------------------------------------------------------
__global__ __launch_bounds__(256) void outT_k(float* __restrict__ out) {
    __shared__ float tile[64][65];
    const int b0 = blockIdx.x * 64;
    const int p  = blockIdx.y;
    const int tid = threadIdx.x;
#pragma unroll
    for (int it = 0; it < 4; it++) {
        int i = it * 256 + tid;
        int cc = i >> 4, q = i & 15;
        float4 v = *(const float4*)(d_outS + (((size_t)cc * NP + p) * NB) + b0 + q * 4);
        tile[cc][q * 4 + 0] = v.x;
        tile[cc][q * 4 + 1] = v.y;
        tile[cc][q * 4 + 2] = v.z;
        tile[cc][q * 4 + 3] = v.w;
    }
    __syncthreads();
#pragma unroll
    for (int it = 0; it < 4; it++) {
        int i = it * 256 + tid;
        int b = i >> 4, q = i & 15;
        float4 w;
        w.x = tile[q * 4 + 0][b];
        w.y = tile[q * 4 + 1][b];
        w.z = tile[q * 4 + 2][b];
        w.w = tile[q * 4 + 3][b];
        *(float4*)(out + (size_t)(b0 + b) * (NP * CF) + (size_t)p * CF + q * 4) = w;
    }
}

// ---------------------------------------------------------------------------
extern "C" void kernel_launch(void* const* d_in, const int* in_sizes, int n_in,
                              void* d_out, int out_size) {
    const float* x        = (const float*)d_in[0];
    const float* decomp_w = (const float*)d_in[1];
    const float* trend_W  = (const float*)d_in[2];
    const float* trend_b  = (const float*)d_in[3];
    const float* seas_W   = (const float*)d_in[4];
    const float* seas_b   = (const float*)d_in[5];
    const float* lagc_W   = (const float*)d_in[6];
    const float* lagc_b   = (const float*)d_in[7];
    const float* wx       = (const float*)d_in[8];
    const float* wy       = (const float*)d_in[9];
    const float* wz       = (const float*)d_in[10];
    const float* W1       = (const float*)d_in[11];
    const float* b1       = (const float*)d_in[12];
    const float* W2       = (const float*)d_in[13];
    const float* b2       = (const float*)d_in[14];
    const float* alpha    = (const float*)d_in[15];
    float* out = (float*)d_out;

    static int n_sm = 0;
    if (n_sm == 0) {
        cudaDeviceGetAttribute(&n_sm, cudaDevAttrMultiProcessorCount, 0);
        if (n_sm <= 0) n_sm = 148;
        cudaFuncSetAttribute(gemm_k, cudaFuncAttributeMaxDynamicSharedMemorySize,
                             NCHUNK * STAGE_B);
    }

    pre_k<<<N_MODB + N_PREPB + N_TRB, 256>>>(x, decomp_w, trend_W, trend_b, seas_W, seas_b,
                                             lagc_W, lagc_b, wx, wy, wz,
                                             W1, b1, W2, b2, alpha);
    gemm_k<<<n_sm, 544, NCHUNK * STAGE_B>>>();
    outT_k<<<dim3(64, 96), 256>>>(out);
}